// round 17
// baseline (speedup 1.0000x reference)
#include <cuda_runtime.h>
#include <cstdint>
#include <math.h>

#define D    128
#define S_MAX 125000
#define EPS  1e-13f

__device__ int g_starts[S_MAX + 1];        // segment start offsets
__device__ uint32_t g_WmT[D * D];          // Wm transposed, tf32 bits: [col][k]

// ---------------------------------------------------------------------------
// Kernel 1: segment starts (int4 scan) + Wm -> tf32 transposed copy.
// ---------------------------------------------------------------------------
__device__ __forceinline__ uint32_t f2tf32(float f) {
    uint32_t r;
    asm("cvt.rna.tf32.f32 %0, %1;" : "=r"(r) : "f"(f));
    return r;
}

__global__ void prep_kernel(const int* __restrict__ idx,
                            const float* __restrict__ Wm,
                            int N, int S) {
    int t  = blockIdx.x * blockDim.x + threadIdx.x;

    // Wm transpose+convert: first 16384 threads, one element each
    if (t < D * D) {
        int k = t >> 7;          // row of Wm
        int c = t & 127;         // col of Wm
        g_WmT[c * D + k] = f2tf32(Wm[k * D + c]);
    }

    int n0 = t * 4;
    if (n0 >= N) return;

    int v0, v1, v2, v3;
    if (n0 + 3 < N) {
        int4 cc = *(const int4*)(idx + n0);
        v0 = cc.x; v1 = cc.y; v2 = cc.z; v3 = cc.w;
    } else {
        v0 = idx[n0];
        v1 = (n0 + 1 < N) ? idx[n0 + 1] : v0;
        v2 = (n0 + 2 < N) ? idx[n0 + 2] : v1;
        v3 = (n0 + 3 < N) ? idx[n0 + 3] : v2;
    }
    int prev = (n0 == 0) ? -1 : idx[n0 - 1];

    int vals[4] = {v0, v1, v2, v3};
    #pragma unroll
    for (int j = 0; j < 4; ++j) {
        if (n0 + j < N) {
            int cur = vals[j];
            for (int s = prev + 1; s <= cur; ++s) g_starts[s] = n0 + j;
            prev = cur;
        }
    }
    if (n0 + 4 >= N) {
        for (int s = prev + 1; s <= S; ++s) g_starts[s] = N;
    }
}

__device__ __forceinline__ float dot4(float4 a, float4 b) {
    return a.x * b.x + a.y * b.y + a.z * b.z + a.w * b.w;
}

__device__ __forceinline__ void mma_tf32(float* c, const uint32_t* a, const uint32_t* b) {
    asm volatile(
        "mma.sync.aligned.m16n8k8.row.col.f32.tf32.tf32.f32 "
        "{%0,%1,%2,%3}, {%4,%5,%6,%7}, {%8,%9}, {%0,%1,%2,%3};\n"
        : "+f"(c[0]), "+f"(c[1]), "+f"(c[2]), "+f"(c[3])
        : "r"(a[0]), "r"(a[1]), "r"(a[2]), "r"(a[3]), "r"(b[0]), "r"(b[1]));
}

__device__ __forceinline__ void cp_async16(uint32_t dst, const float* src) {
    asm volatile("cp.async.cg.shared.global [%0], [%1], 16;" :: "r"(dst), "l"(src));
}
#define CP_COMMIT() asm volatile("cp.async.commit_group;")
#define CP_WAIT(n)  asm volatile("cp.async.wait_group %0;" :: "n"(n))

// ---------------------------------------------------------------------------
// FUSED kernel, BM=64 + cp.async row ring (R15/R16 phase 1, record holder).
// Phase 2: b-frags load DIRECTLY from L2-resident g_WmT (tf32, transposed) --
// no wS smem staging, no per-kt barriers: exactly ONE __syncthreads in the
// whole kernel (the phase boundary). Y holds tf32 bits.
// ---------------------------------------------------------------------------
#define BM 64
#define BN 128
#define BK 32
#define YSTR 36
// dynamic smem words: Y 4*64*36 = 9216 | ring 8w*8slots*128 = 8192 | sg 64
#define SM_Y    0
#define SM_RING 9216
#define SM_SG   (9216 + 8192)
#define SMEM_WORDS (9216 + 8192 + 64)

__global__ void __launch_bounds__(256, 3)
fused_kernel(const float* __restrict__ x,
             const float* __restrict__ w,
             const float* __restrict__ Wg,
             const float* __restrict__ bgp,
             const float* __restrict__ bm,
             float* __restrict__ out, int S) {
    extern __shared__ float sm[];
    uint32_t* Y  = (uint32_t*)(sm + SM_Y);     // [4][64][36] tf32 bits
    float*    SG = sm + SM_SG;                 // [64]

    int tid  = threadIdx.x;
    int wid  = tid >> 5;
    int lane = tid & 31;
    int segbase = blockIdx.x * BM;

    // ===================== Phase 1: aggregation into SMEM =====================
    {
        int q   = lane >> 3;
        int pm1 = q ^ 1, pm2 = q ^ 2, pm3 = q ^ 3;
        float4 wg  = *(const float4*)(Wg + lane * 4);
        float  bg0 = bgp[0];

        int chunk = lane >> 3;            // K-chunk this lane's columns live in
        int ccol  = (lane & 7) * 4;       // column within chunk

        // per-warp ring
        const float* ringw = sm + SM_RING + wid * 1024;           // reads
        uint32_t ring_u32 = (uint32_t)__cvta_generic_to_shared(sm + SM_RING)
                          + wid * 4096 + (lane << 4);             // writes (bytes)

        int s_first = segbase + wid * 8;
        int sf = s_first; if (sf > S) sf = S;
        int se = s_first + 8; if (se > S) se = S; if (se < sf) se = sf;
        int rs = g_starts[sf];
        int re = g_starts[se];
        int ifetch = rs;

        int r0 = rs;
        for (int i = 0; i < 8; ++i) {
            int s     = s_first + i;
            int local = wid * 8 + i;
            int r1  = (s < S) ? g_starts[s + 1] : r0;
            int len = r1 - r0;

            float4 acc = make_float4(0.f, 0.f, 0.f, 0.f);
            float  denom = 0.f;

            for (int base = 0; base < len; base += 4) {
                int b = r0 + base;
                // issue rows [ifetch, min(b+8,re)) into the ring
                int tgt = b + 8; if (tgt > re) tgt = re;
                for (; ifetch < tgt; ++ifetch) {
                    cp_async16(ring_u32 + ((ifetch & 7) << 9),
                               x + ((size_t)ifetch << 7) + (lane << 2));
                    CP_COMMIT();
                }
                if (b + 8 > re) { CP_WAIT(0); } else { CP_WAIT(4); }

                int rA = base + q;
                int rB = base + pm1;
                int rC = base + pm2;
                int rD = base + pm3;

                float4 v0 = make_float4(0.f,0.f,0.f,0.f), v1 = v0, v2 = v0, v3 = v0;
                if (rA < len) v0 = *(const float4*)(ringw + (((r0 + rA) & 7) << 7) + (lane << 2));
                if (rB < len) v1 = *(const float4*)(ringw + (((r0 + rB) & 7) << 7) + (lane << 2));
                if (rC < len) v2 = *(const float4*)(ringw + (((r0 + rC) & 7) << 7) + (lane << 2));
                if (rD < len) v3 = *(const float4*)(ringw + (((r0 + rD) & 7) << 7) + (lane << 2));
                float wr = (rA < len) ? w[r0 + rA] : 0.f;

                float p0 = dot4(v0, wg);
                float p1 = dot4(v1, wg);
                float p2 = dot4(v2, wg);
                float p3 = dot4(v3, wg);

                float t01 = p0 + __shfl_xor_sync(0xffffffffu, p1, 8);
                float t23 = p2 + __shfl_xor_sync(0xffffffffu, p3, 8);
                float t   = t01 + __shfl_xor_sync(0xffffffffu, t23, 16);
                t += __shfl_xor_sync(0xffffffffu, t, 1);
                t += __shfl_xor_sync(0xffffffffu, t, 2);
                t += __shfl_xor_sync(0xffffffffu, t, 4);

                float g = wr * __expf(t + bg0);
                denom += g;

                float g1 = __shfl_xor_sync(0xffffffffu, g, 8);
                float g2 = __shfl_xor_sync(0xffffffffu, g, 16);
                float g3 = __shfl_xor_sync(0xffffffffu, g, 24);

                acc.x += g * v0.x + g1 * v1.x + g2 * v2.x + g3 * v3.x;
                acc.y += g * v0.y + g1 * v1.y + g2 * v2.y + g3 * v3.y;
                acc.z += g * v0.z + g1 * v1.z + g2 * v2.z + g3 * v3.z;
                acc.w += g * v0.w + g1 * v1.w + g2 * v2.w + g3 * v3.w;
            }

            denom += __shfl_xor_sync(0xffffffffu, denom, 8);
            denom += __shfl_xor_sync(0xffffffffu, denom, 16);

            float inv = 1.f / (denom + EPS);
            uint4 o;
            o.x = f2tf32(acc.x * inv); o.y = f2tf32(acc.y * inv);
            o.z = f2tf32(acc.z * inv); o.w = f2tf32(acc.w * inv);
            *(uint4*)(Y + chunk * (BM * YSTR) + local * YSTR + ccol) = o;
            if (lane == 0) SG[local] = denom * inv;

            r0 = r1;
        }

        CP_WAIT(0);   // drain pending cp.async before smem reuse / exit
    }

    __syncthreads();   // the ONLY block-wide barrier: Y/SG complete

    // ===================== Phase 2: tf32 MMA gemm (b from global) =====================
    int warp_m = wid & 1;     // 2 warps along M (32 rows each)
    int warp_n = wid >> 1;    // 4 warps along N (32 cols each)
    int grp = lane >> 2;
    int tg  = lane & 3;

    // per-thread base pointers into transposed tf32 Wm: col = warp_n*32+nf*8+grp
    const uint32_t* wt0 = g_WmT + (warp_n * 32 + 0 * 8 + grp) * D + tg;
    const uint32_t* wt1 = g_WmT + (warp_n * 32 + 1 * 8 + grp) * D + tg;
    const uint32_t* wt2 = g_WmT + (warp_n * 32 + 2 * 8 + grp) * D + tg;
    const uint32_t* wt3 = g_WmT + (warp_n * 32 + 3 * 8 + grp) * D + tg;

    float c[2][4][4];
    #pragma unroll
    for (int mf = 0; mf < 2; ++mf)
        #pragma unroll
        for (int nf = 0; nf < 4; ++nf)
            #pragma unroll
            for (int i = 0; i < 4; ++i) c[mf][nf][i] = 0.f;

    #pragma unroll
    for (int kt = 0; kt < D; kt += BK) {
        const uint32_t* Yc = Y + (kt >> 5) * (BM * YSTR);

        #pragma unroll
        for (int ks = 0; ks < BK; ks += 8) {
            int k = kt + ks;
            uint32_t a[2][4];
            uint32_t b[4][2];
            #pragma unroll
            for (int mf = 0; mf < 2; ++mf) {
                int r = warp_m * 32 + mf * 16;
                a[mf][0] = Yc[(r + grp    ) * YSTR + ks + tg    ];
                a[mf][1] = Yc[(r + grp + 8) * YSTR + ks + tg    ];
                a[mf][2] = Yc[(r + grp    ) * YSTR + ks + tg + 4];
                a[mf][3] = Yc[(r + grp + 8) * YSTR + ks + tg + 4];
            }
            b[0][0] = wt0[k];     b[0][1] = wt0[k + 4];
            b[1][0] = wt1[k];     b[1][1] = wt1[k + 4];
            b[2][0] = wt2[k];     b[2][1] = wt2[k + 4];
            b[3][0] = wt3[k];     b[3][1] = wt3[k + 4];
            #pragma unroll
            for (int mf = 0; mf < 2; ++mf)
                #pragma unroll
                for (int nf = 0; nf < 4; ++nf)
                    mma_tf32(c[mf][nf], a[mf], b[nf]);
        }
    }

    // Epilogue: out = c + sg[row] * bm[col]
    #pragma unroll
    for (int mf = 0; mf < 2; ++mf) {
        int lrow0 = warp_m * 32 + mf * 16 + grp;
        int lrow1 = lrow0 + 8;
        int row0 = segbase + lrow0;
        int row1 = segbase + lrow1;
        float sgA = SG[lrow0];
        float sgB = SG[lrow1];
        #pragma unroll
        for (int nf = 0; nf < 4; ++nf) {
            int col = warp_n * 32 + nf * 8 + tg * 2;
            float b0 = bm[col], b1 = bm[col + 1];
            if (row0 < S) {
                float2 o;
                o.x = c[mf][nf][0] + sgA * b0;
                o.y = c[mf][nf][1] + sgA * b1;
                *(float2*)(out + (size_t)row0 * D + col) = o;
            }
            if (row1 < S) {
                float2 o;
                o.x = c[mf][nf][2] + sgB * b0;
                o.y = c[mf][nf][3] + sgB * b1;
                *(float2*)(out + (size_t)row1 * D + col) = o;
            }
        }
    }
}

// ---------------------------------------------------------------------------
extern "C" void kernel_launch(void* const* d_in, const int* in_sizes, int n_in,
                              void* d_out, int out_size) {
    const float* x   = (const float*)d_in[0];
    const int*   idx = (const int*)  d_in[1];
    const float* w   = (const float*)d_in[2];
    const float* Wg  = (const float*)d_in[3];
    const float* bg  = (const float*)d_in[4];
    const float* Wm  = (const float*)d_in[5];
    const float* bm  = (const float*)d_in[6];
    float* out = (float*)d_out;

    int N = in_sizes[1];
    int S = out_size / D;

    int quads = (N + 3) / 4;
    prep_kernel<<<(quads + 255) / 256, 256>>>(idx, Wm, N, S);

    static int smem_set = 0;
    if (!smem_set) {
        cudaFuncSetAttribute(fused_kernel,
                             cudaFuncAttributeMaxDynamicSharedMemorySize,
                             SMEM_WORDS * 4);
        smem_set = 1;
    }
    int blocks = (S + BM - 1) / BM;
    fused_kernel<<<blocks, 256, SMEM_WORDS * 4>>>(x, w, Wg, bg, bm, out, S);
}